// round 7
// baseline (speedup 1.0000x reference)
#include <cuda_runtime.h>
#include <cuda_fp16.h>
#include <cstdint>
#include <cfloat>

#define N_ROWS 65536
#define DIM    1024
#define KCB    8192

#define TAU      0.06f     // fp16 margin threshold (~12 sigma)
#define TAU2     2.0e-3f   // refine candidate window (fp32-noise scale)
#define WL_CAP   8192
#define CAND_CAP 32

// ---- HMMA GEMM tiling ----
#define BM 128
#define BN 128
#define KC 128
#define N_TILES (KCB / BN)                       // 64
#define CHUNKS_PER_TILE (DIM / KC)               // 8
#define TOTAL_CHUNKS (N_TILES * CHUNKS_PER_TILE) // 512
#define GEMM_THREADS 256

// ---- dynamic SMEM layout (bytes) ----
// chunk = A(128x128 fp16) + B(128x128 fp16) = 64KB, stored as 4 x 16KB
// SW128 subtiles: [A k0-63][A k64-127][B k0-63][B k64-127]
#define SUB_BYTES    16384
#define SM_A_OFF     0
#define SM_B_OFF     32768
#define STAGE_BYTES  65536
#define NSTAGES      3
#define SM_EPI       (NSTAGES * STAGE_BYTES)     // 196608
#define EPI_B        0                           // float[128*4]
#define EPI_S        2048
#define EPI_I        4096
#define GEMM_SMEM    (SM_EPI + 6144)             // 202752

// ---- scratch (__device__ globals; allocation-free rule) ----
__device__ __half g_zh[(size_t)N_ROWS * DIM];    // 128 MB
__device__ __half g_ch[(size_t)KCB * DIM];       // 16 MB
__device__ float  g_cbT[(size_t)KCB * DIM];      // 32 MB fp32 (refine + gather)
__device__ int    g_argmin[N_ROWS];
__device__ int    g_wl[WL_CAP];
__device__ int    g_wl_count;

// ============================ helpers ============================
__device__ __forceinline__ uint32_t smem_to_u32(const void* p) {
    uint32_t a;
    asm("{ .reg .u64 t; cvta.to.shared.u64 t, %1; cvt.u32.u64 %0, t; }" : "=r"(a) : "l"(p));
    return a;
}
#define SWZ128(o) ((o) ^ (((o) >> 3) & 0x70))

#define CP_ASYNC16(sm, g) \
    asm volatile("cp.async.cg.shared.global [%0], [%1], 16;" :: "r"(sm), "l"(g) : "memory")
#define CP_COMMIT()  asm volatile("cp.async.commit_group;" ::: "memory")
#define CP_WAIT2()   asm volatile("cp.async.wait_group 2;" ::: "memory")
#define CP_WAIT1()   asm volatile("cp.async.wait_group 1;" ::: "memory")
#define CP_WAIT0()   asm volatile("cp.async.wait_group 0;" ::: "memory")

#define LDMATRIX_X4(r0, r1, r2, r3, a) \
    asm volatile("ldmatrix.sync.aligned.m8n8.x4.shared.b16 {%0,%1,%2,%3}, [%4];" \
                 : "=r"(r0), "=r"(r1), "=r"(r2), "=r"(r3) : "r"(a))

#define MMA_F16(c0, c1, c2, c3, a0, a1, a2, a3, b0, b1) \
    asm volatile("mma.sync.aligned.m16n8k16.row.col.f32.f16.f16.f32 " \
                 "{%0,%1,%2,%3}, {%4,%5,%6,%7}, {%8,%9}, {%0,%1,%2,%3};" \
                 : "+f"(c0), "+f"(c1), "+f"(c2), "+f"(c3) \
                 : "r"(a0), "r"(a1), "r"(a2), "r"(a3), "r"(b0), "r"(b1))

// ---------------------------------------------------------------------------
// Prep 1: transpose codebook -> g_cbT fp32 + g_ch fp16; reset worklist.
// ---------------------------------------------------------------------------
__global__ void vq_prep_cb(const float* __restrict__ cb) {
    if (blockIdx.x == 0 && blockIdx.y == 0 && threadIdx.x == 0 && threadIdx.y == 0)
        g_wl_count = 0;
    __shared__ float tile[32][33];
    const int kBase = blockIdx.x * 32;
    const int dBase = blockIdx.y * 32;
    const int tx = threadIdx.x, ty = threadIdx.y;
#pragma unroll
    for (int i = 0; i < 4; i++)
        tile[ty + i * 8][tx] = cb[(size_t)(dBase + ty + i * 8) * KCB + (kBase + tx)];
    __syncthreads();
#pragma unroll
    for (int i = 0; i < 4; i++) {
        const float v = tile[tx][ty + i * 8];
        const size_t o = (size_t)(kBase + ty + i * 8) * DIM + (dBase + tx);
        g_cbT[o] = v;
        g_ch[o] = __float2half(v);
    }
}

// ---------------------------------------------------------------------------
// Prep 2: z -> fp16.
// ---------------------------------------------------------------------------
__global__ void vq_prep_z(const float* __restrict__ z) {
    const size_t total4 = (size_t)N_ROWS * DIM / 4;
    const size_t stride = (size_t)gridDim.x * blockDim.x;
    const float4* z4 = (const float4*)z;
    __half2* h2 = (__half2*)g_zh;
    for (size_t t = (size_t)blockIdx.x * blockDim.x + threadIdx.x; t < total4; t += stride) {
        const float4 v = z4[t];
        h2[t * 2 + 0] = __floats2half2_rn(v.x, v.y);
        h2[t * 2 + 1] = __floats2half2_rn(v.z, v.w);
    }
}

// ---------------------------------------------------------------------------
// Main: single-pass fp16 HMMA GEMM (KC=128 chunks) + fused argmin w/ margin.
// ---------------------------------------------------------------------------
__global__ __launch_bounds__(GEMM_THREADS)
void vq_hmma_kernel() {
    extern __shared__ char smem[];
    const uint32_t sb = smem_to_u32(smem);
    const int tid  = threadIdx.x;
    const int wid  = tid >> 5;
    const int lane = tid & 31;
    const int wm   = wid >> 2;            // 0..1 (M group of 64)
    const int wn   = wid & 3;             // 0..3 (N group of 32)
    const int t4   = lane >> 2;           // 0..7
    const int tq   = lane & 3;            // 0..3
    const int rowBase = blockIdx.x * BM;

    // per-chunk loader: 16 x 16B cp.async per thread (A k-halves + B k-halves)
    auto load_chunk = [&](int C) {
        const int nt = C / CHUNKS_PER_TILE, c = C % CHUNKS_PER_TILE;
        const uint32_t stage = sb + (C % NSTAGES) * STAGE_BYTES;
        const int koff = c * KC;
        const int ntBase = nt * BN;
#pragma unroll
        for (int i = 0; i < 4; i++) {
            const int sg = tid + i * 256;        // 0..1023
            const int row = sg >> 3, sc = sg & 7;
            const uint32_t so = SWZ128(row * 128 + sc * 16);
#pragma unroll
            for (int h = 0; h < 2; h++) {
                const int col = koff + h * 64 + sc * 8;
                CP_ASYNC16(stage + SM_A_OFF + h * SUB_BYTES + so,
                           g_zh + (size_t)(rowBase + row) * DIM + col);
                CP_ASYNC16(stage + SM_B_OFF + h * SUB_BYTES + so,
                           g_ch + (size_t)(ntBase + row) * DIM + col);
            }
        }
        CP_COMMIT();
    };

    float acc[4][4][4];
    float rBest = FLT_MAX, rSec = FLT_MAX;
    int   rIdx = 0x7FFFFFFF;

    // ldmatrix lane-address components
    const int am  = lane >> 3;            // matrix id 0..3
    const int ar  = lane & 7;
    const int aRow = ((am & 1) << 3) + ar;
    const int aColB = (am >> 1) << 4;
    const int bRow = ((am >> 1) << 3) + ar;
    const int bColB = (am & 1) << 4;

    load_chunk(0);
    load_chunk(1);
    load_chunk(2);

    for (int C = 0; C < TOTAL_CHUNKS; C++) {
        const int nt = C / CHUNKS_PER_TILE, c = C % CHUNKS_PER_TILE;

        const int remaining = TOTAL_CHUNKS - 1 - C;
        if (remaining >= 2)      { CP_WAIT2(); }
        else if (remaining == 1) { CP_WAIT1(); }
        else                     { CP_WAIT0(); }
        __syncthreads();

        if (c == 0) {
#pragma unroll
            for (int mi = 0; mi < 4; mi++)
#pragma unroll
                for (int ni = 0; ni < 4; ni++)
#pragma unroll
                    for (int r = 0; r < 4; r++) acc[mi][ni][r] = 0.0f;
        }

        const uint32_t stage = sb + (C % NSTAGES) * STAGE_BYTES;

#pragma unroll
        for (int ks = 0; ks < 8; ks++) {
            const int khalf = ks >> 2;
            const int kb = (ks & 3) * 32;         // 16 fp16 = 32B per k-step
            const uint32_t aB = stage + SM_A_OFF + khalf * SUB_BYTES;
            const uint32_t bB = stage + SM_B_OFF + khalf * SUB_BYTES;
            uint32_t af[16], bf[16];

#pragma unroll
            for (int mi = 0; mi < 4; mi++) {
                const int row = wm * 64 + mi * 16 + aRow;
                const uint32_t ad = aB + SWZ128(row * 128 + kb + aColB);
                LDMATRIX_X4(af[mi*4+0], af[mi*4+1], af[mi*4+2], af[mi*4+3], ad);
            }
#pragma unroll
            for (int np = 0; np < 2; np++) {
                const int nrow = wn * 32 + np * 16 + bRow;
                const uint32_t bd = bB + SWZ128(nrow * 128 + kb + bColB);
                LDMATRIX_X4(bf[np*8+0], bf[np*8+1], bf[np*8+4], bf[np*8+5], bd);
            }

#pragma unroll
            for (int mi = 0; mi < 4; mi++)
#pragma unroll
                for (int ni = 0; ni < 4; ni++)
                    MMA_F16(acc[mi][ni][0], acc[mi][ni][1], acc[mi][ni][2], acc[mi][ni][3],
                            af[mi*4+0], af[mi*4+1], af[mi*4+2], af[mi*4+3],
                            bf[ni*4+0], bf[ni*4+1]);
        }
        __syncthreads();

        if (C + 3 < TOTAL_CHUNKS) load_chunk(C + 3);

        // ---- n-tile epilogue ----
        if (c == CHUNKS_PER_TILE - 1) {
            float* eB = (float*)(smem + SM_EPI + EPI_B);
            float* eS = (float*)(smem + SM_EPI + EPI_S);
            int*   eI = (int*)(smem + SM_EPI + EPI_I);
            const int colBase = nt * BN + wn * 32 + tq * 2;

#pragma unroll
            for (int mi = 0; mi < 4; mi++) {
#pragma unroll
                for (int half = 0; half < 2; half++) {
                    const int row = wm * 64 + mi * 16 + half * 8 + t4;
                    float b = FLT_MAX, sv = FLT_MAX;
                    int   bi = 0x7FFFFFFF;
#pragma unroll
                    for (int ni = 0; ni < 4; ni++) {
#pragma unroll
                        for (int cc = 0; cc < 2; cc++) {
                            const float v = acc[mi][ni][half * 2 + cc];
                            const int col = colBase + ni * 8 + cc;
                            if (v < b) { sv = b; b = v; bi = col; }
                            else       { sv = fminf(sv, v); }
                        }
                    }
#pragma unroll
                    for (int off = 1; off <= 2; off <<= 1) {
                        const float ob = __shfl_xor_sync(0xFFFFFFFFu, b, off);
                        const float os = __shfl_xor_sync(0xFFFFFFFFu, sv, off);
                        const int   oi = __shfl_xor_sync(0xFFFFFFFFu, bi, off);
                        if (ob < b || (ob == b && oi < bi)) {
                            sv = fminf(b, os); b = ob; bi = oi;
                        } else {
                            sv = fminf(sv, ob);
                        }
                    }
                    if (tq == 0) {
                        eB[row * 4 + wn] = b;
                        eS[row * 4 + wn] = sv;
                        eI[row * 4 + wn] = bi;
                    }
                }
            }
            __syncthreads();
            if (tid < BM) {
#pragma unroll
                for (int w = 0; w < 4; w++) {
                    const float b = eB[tid * 4 + w];
                    const float sv = eS[tid * 4 + w];
                    const int   bi = eI[tid * 4 + w];
                    if (b < rBest || (b == rBest && bi < rIdx)) {
                        rSec = fminf(rBest, sv);
                        rBest = b; rIdx = bi;
                    } else {
                        rSec = fminf(rSec, fminf(b, sv));
                    }
                }
            }
            __syncthreads();
        }
    }

    if (tid < BM) {
        const int row = rowBase + tid;
        g_argmin[row] = rIdx;
        if (rSec - rBest < TAU) {
            const int p = atomicAdd(&g_wl_count, 1);
            if (p < WL_CAP) g_wl[p] = row;
        }
    }
}

// ---------------------------------------------------------------------------
// Refine: 4 rows/CTA, warp = (row, codebook-half). z row in registers.
// ---------------------------------------------------------------------------
#define RB 4
__global__ __launch_bounds__(256)
void vq_refine_kernel(const float* __restrict__ A) {
    __shared__ float  zs[RB][DIM];
    __shared__ int    rws[RB];
    __shared__ float  hmin[RB][2];
    __shared__ int    hcnt[RB][2];
    __shared__ int    hidx[RB][2][CAND_CAP];
    __shared__ float  hval[RB][2][CAND_CAP];

    const int tid  = threadIdx.x;
    const int lane = tid & 31;
    const int wrp  = tid >> 5;
    const int r    = wrp >> 1;
    const int h    = wrp & 1;
    const int cnt  = min(g_wl_count, WL_CAP);
    const int nB   = (cnt + RB - 1) / RB;

    for (int b = blockIdx.x; b < nB; b += gridDim.x) {
        if (tid < RB) rws[tid] = (b * RB + tid < cnt) ? g_wl[b * RB + tid] : -1;
        if (tid < RB * 2) hcnt[tid >> 1][tid & 1] = 0;
        __syncthreads();

        for (int i = tid; i < RB * DIM; i += 256) {
            const int rr = i >> 10, dd = i & 1023;
            zs[rr][dd] = (rws[rr] >= 0) ? A[(size_t)rws[rr] * DIM + dd] : 0.0f;
        }
        __syncthreads();

        const bool active = rws[r] >= 0;

        float4 zr[8];
#pragma unroll
        for (int q = 0; q < 8; q++)
            zr[q] = ((const float4*)zs[r])[lane + 32 * q];

        float wmin = FLT_MAX;
        const int kBeg = h * (KCB / 2), kEnd = kBeg + KCB / 2;
        for (int k = kBeg; k < kEnd; k++) {
            const float4* cw = (const float4*)(g_cbT + (size_t)k * DIM);
            float s = 0.0f;
#pragma unroll
            for (int q = 0; q < 8; q++) {
                const float4 c = cw[lane + 32 * q];
                s = fmaf(c.x, zr[q].x, s);
                s = fmaf(c.y, zr[q].y, s);
                s = fmaf(c.z, zr[q].z, s);
                s = fmaf(c.w, zr[q].w, s);
            }
#pragma unroll
            for (int off = 16; off > 0; off >>= 1)
                s += __shfl_down_sync(0xFFFFFFFFu, s, off);
            if (lane == 0 && active) {
                if (s < wmin + TAU2) {
                    const int p = hcnt[r][h];
                    if (p < CAND_CAP) {
                        hidx[r][h][p] = k;
                        hval[r][h][p] = s;
                        hcnt[r][h] = p + 1;
                    }
                    if (s < wmin) wmin = s;
                }
            }
        }
        if (lane == 0) hmin[r][h] = wmin;
        __syncthreads();

        if (h == 0 && active) {
            const float bmin = fminf(hmin[r][0], hmin[r][1]);
            double bestV = 1e300;
            int    bestI = 0x7FFFFFFF;
#pragma unroll
            for (int hh = 0; hh < 2; hh++) {
                const int nc = min(hcnt[r][hh], CAND_CAP);
                for (int ci = 0; ci < nc; ci++) {
                    const float v = hval[r][hh][ci];
                    if (v >= bmin + TAU2) continue;
                    const int k = hidx[r][hh][ci];
                    const float* cw = g_cbT + (size_t)k * DIM;
                    double sd = 0.0;
#pragma unroll
                    for (int q = 0; q < 8; q++) {
#pragma unroll
                        for (int e = 0; e < 4; e++) {
                            const int d = (lane + 32 * q) * 4 + e;
                            sd += (double)cw[d] * (double)zs[r][d];
                        }
                    }
#pragma unroll
                    for (int off = 16; off > 0; off >>= 1)
                        sd += __shfl_down_sync(0xFFFFFFFFu, sd, off);
                    if (lane == 0) {
                        if (sd < bestV || (sd == bestV && k < bestI)) {
                            bestV = sd; bestI = k;
                        }
                    }
                }
            }
            if (lane == 0) g_argmin[rws[r]] = bestI;
        }
        __syncthreads();
    }
}

// ---------------------------------------------------------------------------
// Gather: out[n][:] = g_cbT[argmin[n]][:]
// ---------------------------------------------------------------------------
__global__ void vq_gather_kernel(float* __restrict__ out) {
    const int n = blockIdx.x;
    const int idx = g_argmin[n];
    const float4* src = (const float4*)(g_cbT + (size_t)idx * DIM);
    float4* dst = (float4*)(out + (size_t)n * DIM);
    dst[threadIdx.x] = src[threadIdx.x];
}

// ---------------------------------------------------------------------------
extern "C" void kernel_launch(void* const* d_in, const int* in_sizes, int n_in,
                              void* d_out, int out_size) {
    const float* z  = (const float*)d_in[0];
    const float* cb = (const float*)d_in[1];
    float* out = (float*)d_out;

    cudaFuncSetAttribute(vq_hmma_kernel, cudaFuncAttributeMaxDynamicSharedMemorySize, GEMM_SMEM);

    dim3 tgrid(KCB / 32, DIM / 32);
    dim3 tblk(32, 8);
    vq_prep_cb<<<tgrid, tblk>>>(cb);
    vq_prep_z<<<8192, 256>>>(z);

    vq_hmma_kernel<<<N_ROWS / BM, GEMM_THREADS, GEMM_SMEM>>>();

    vq_refine_kernel<<<592, 256>>>(z);
    vq_gather_kernel<<<N_ROWS, 256>>>(out);
}

// round 9
// speedup vs baseline: 2.2502x; 2.2502x over previous
#include <cuda_runtime.h>
#include <cuda_bf16.h>
#include <cstdint>
#include <cfloat>

#define N_ROWS 65536
#define DIM    1024
#define KCB    8192

#define TAU1     0.40f     // 1-pass bf16 margin threshold (~10+ sigma of bf16 noise)
#define TAU2     2.0e-3f   // 3-pass margin threshold
#define TAU3     2.0e-3f   // exact-refine candidate window
#define WL_CAP   16384     // expected flagged ~10.5k (16% of rows); +75 sigma headroom
#define WL2_CAP  2048
#define MAX_CAND 64

#define BM 128
#define BN 128
#define KC 64
#define N_TILES (KCB / BN)                        // 64
#define CHUNKS_PER_TILE (DIM / KC)                // 16
#define TOTAL_CHUNKS (N_TILES * CHUNKS_PER_TILE)  // 1024
#define GEMM_THREADS 256

// ---- hmma1 SMEM layout (1-pass): stage = A(16K) + B(16K) ----
#define H1_STAGE   32768
#define H1_A       0
#define H1_B       16384
#define H1_EPI     (2 * H1_STAGE)                 // 65536
#define EPI_B      0
#define EPI_S      2048
#define EPI_I      4096
#define H1_SMEM    (H1_EPI + 6144)                // 71680

// ---- hmma2 SMEM layout (3-pass): stage = Ah+Al+Bh+Bl (64K) ----
#define H2_STAGE   65536
#define H2_A_HI    0
#define H2_A_LO    16384
#define H2_B_HI    32768
#define H2_B_LO    49152
#define H2_EPI     (2 * H2_STAGE)                 // 131072
#define H2_SMEM    (H2_EPI + 6144)                // 137216

// ---- scratch (__device__ globals; allocation-free rule) ----
__device__ __nv_bfloat16 g_zh[(size_t)N_ROWS * DIM];    // 128 MB
__device__ __nv_bfloat16 g_cbh[(size_t)KCB * DIM];      // 16 MB
__device__ __nv_bfloat16 g_cbl[(size_t)KCB * DIM];      // 16 MB
__device__ float         g_cbT[(size_t)KCB * DIM];      // 32 MB
__device__ __nv_bfloat16 g_rzh[(size_t)WL_CAP * DIM];   // 32 MB compact flagged rows (hi)
__device__ __nv_bfloat16 g_rzl[(size_t)WL_CAP * DIM];   // 32 MB (lo)
__device__ int g_argmin[N_ROWS];
__device__ int g_wl[WL_CAP];
__device__ int g_wl_count;
__device__ int g_wl2[WL2_CAP];
__device__ int g_wl2_count;

// ============================ helpers ============================
__device__ __forceinline__ uint32_t smem_to_u32(const void* p) {
    uint32_t a;
    asm("{ .reg .u64 t; cvta.to.shared.u64 t, %1; cvt.u32.u64 %0, t; }" : "=r"(a) : "l"(p));
    return a;
}
#define SWZ128(o) ((o) ^ (((o) >> 3) & 0x70))

#define CP_ASYNC16(sm, g) \
    asm volatile("cp.async.cg.shared.global [%0], [%1], 16;" :: "r"(sm), "l"(g) : "memory")
#define CP_COMMIT()  asm volatile("cp.async.commit_group;" ::: "memory")
#define CP_WAIT1()   asm volatile("cp.async.wait_group 1;" ::: "memory")
#define CP_WAIT0()   asm volatile("cp.async.wait_group 0;" ::: "memory")

#define LDMATRIX_X4(r0, r1, r2, r3, a) \
    asm volatile("ldmatrix.sync.aligned.m8n8.x4.shared.b16 {%0,%1,%2,%3}, [%4];" \
                 : "=r"(r0), "=r"(r1), "=r"(r2), "=r"(r3) : "r"(a))

#define MMA_BF16(c0, c1, c2, c3, a0, a1, a2, a3, b0, b1) \
    asm volatile("mma.sync.aligned.m16n8k16.row.col.f32.bf16.bf16.f32 " \
                 "{%0,%1,%2,%3}, {%4,%5,%6,%7}, {%8,%9}, {%0,%1,%2,%3};" \
                 : "+f"(c0), "+f"(c1), "+f"(c2), "+f"(c3) \
                 : "r"(a0), "r"(a1), "r"(a2), "r"(a3), "r"(b0), "r"(b1))

// ---------------------------------------------------------------------------
// Prep 1: transpose codebook -> cbT fp32 + cbh/cbl bf16; reset worklists.
// ---------------------------------------------------------------------------
__global__ void vq_prep_cb(const float* __restrict__ cb) {
    if (blockIdx.x == 0 && blockIdx.y == 0 && threadIdx.x == 0 && threadIdx.y == 0) {
        g_wl_count = 0;
        g_wl2_count = 0;
    }
    __shared__ float tile[32][33];
    const int kBase = blockIdx.x * 32;
    const int dBase = blockIdx.y * 32;
    const int tx = threadIdx.x, ty = threadIdx.y;
#pragma unroll
    for (int i = 0; i < 4; i++)
        tile[ty + i * 8][tx] = cb[(size_t)(dBase + ty + i * 8) * KCB + (kBase + tx)];
    __syncthreads();
#pragma unroll
    for (int i = 0; i < 4; i++) {
        const float v = tile[tx][ty + i * 8];
        const size_t o = (size_t)(kBase + ty + i * 8) * DIM + (dBase + tx);
        g_cbT[o] = v;
        const __nv_bfloat16 h = __float2bfloat16(v);
        g_cbh[o] = h;
        g_cbl[o] = __float2bfloat16(v - __bfloat162float(h));
    }
}

// ---------------------------------------------------------------------------
// Prep 2: z -> bf16 (hi only).
// ---------------------------------------------------------------------------
__global__ void vq_prep_z(const float* __restrict__ z) {
    const size_t total4 = (size_t)N_ROWS * DIM / 4;
    const size_t stride = (size_t)gridDim.x * blockDim.x;
    const float4* z4 = (const float4*)z;
    __nv_bfloat162* h2 = (__nv_bfloat162*)g_zh;
    for (size_t t = (size_t)blockIdx.x * blockDim.x + threadIdx.x; t < total4; t += stride) {
        const float4 v = z4[t];
        h2[t * 2 + 0] = __nv_bfloat162(__float2bfloat16(v.x), __float2bfloat16(v.y));
        h2[t * 2 + 1] = __nv_bfloat162(__float2bfloat16(v.z), __float2bfloat16(v.w));
    }
}

// ---------------------------------------------------------------------------
// hmma1: single-pass bf16 GEMM + fused argmin with runner-up margin.
// ---------------------------------------------------------------------------
__global__ __launch_bounds__(GEMM_THREADS, 2)
void vq_hmma1_kernel() {
    extern __shared__ char smem[];
    const uint32_t sb = smem_to_u32(smem);
    const int tid  = threadIdx.x;
    const int wid  = tid >> 5;
    const int lane = tid & 31;
    const int wm   = wid >> 2;
    const int wn   = wid & 3;
    const int t4   = lane >> 2;
    const int tq   = lane & 3;
    const int rowBase = blockIdx.x * BM;

    auto load_chunk = [&](int C) {
        const int nt = C >> 4, c = C & 15, s = C & 1;
        const uint32_t stage = sb + s * H1_STAGE;
        const int koff = c * KC;
        const int ntBase = nt * BN;
#pragma unroll
        for (int i = 0; i < 4; i++) {
            const int sg = tid + i * 256;
            const int row = sg >> 3, sc = sg & 7;
            const uint32_t so = SWZ128(row * 128 + sc * 16);
            CP_ASYNC16(stage + H1_A + so, g_zh + (size_t)(rowBase + row) * DIM + koff + sc * 8);
            CP_ASYNC16(stage + H1_B + so, g_cbh + (size_t)(ntBase + row) * DIM + koff + sc * 8);
        }
        CP_COMMIT();
    };

    float acc[4][4][4];
    float rBest = FLT_MAX, rSec = FLT_MAX;
    int   rIdx = 0x7FFFFFFF;

    const int am  = lane >> 3;
    const int ar  = lane & 7;
    const int aRow = ((am & 1) << 3) + ar;
    const int aColB = (am >> 1) << 4;
    const int bRow = ((am >> 1) << 3) + ar;
    const int bColB = (am & 1) << 4;

    load_chunk(0);
    load_chunk(1);

    for (int C = 0; C < TOTAL_CHUNKS; C++) {
        const int s = C & 1, nt = C >> 4, c = C & 15;
        if (C < TOTAL_CHUNKS - 1) { CP_WAIT1(); } else { CP_WAIT0(); }
        __syncthreads();

        if (c == 0) {
#pragma unroll
            for (int mi = 0; mi < 4; mi++)
#pragma unroll
                for (int ni = 0; ni < 4; ni++)
#pragma unroll
                    for (int r = 0; r < 4; r++) acc[mi][ni][r] = 0.0f;
        }

        const uint32_t aB = sb + s * H1_STAGE + H1_A;
        const uint32_t bB = sb + s * H1_STAGE + H1_B;

#pragma unroll
        for (int ks = 0; ks < 4; ks++) {
            const int kb = ks * 32;
            uint32_t af[16], bf[16];
#pragma unroll
            for (int mi = 0; mi < 4; mi++) {
                const int row = wm * 64 + mi * 16 + aRow;
                LDMATRIX_X4(af[mi*4+0], af[mi*4+1], af[mi*4+2], af[mi*4+3],
                            aB + SWZ128(row * 128 + kb + aColB));
            }
#pragma unroll
            for (int np = 0; np < 2; np++) {
                const int nrow = wn * 32 + np * 16 + bRow;
                LDMATRIX_X4(bf[np*8+0], bf[np*8+1], bf[np*8+4], bf[np*8+5],
                            bB + SWZ128(nrow * 128 + kb + bColB));
            }
#pragma unroll
            for (int mi = 0; mi < 4; mi++)
#pragma unroll
                for (int ni = 0; ni < 4; ni++)
                    MMA_BF16(acc[mi][ni][0], acc[mi][ni][1], acc[mi][ni][2], acc[mi][ni][3],
                             af[mi*4+0], af[mi*4+1], af[mi*4+2], af[mi*4+3],
                             bf[ni*4+0], bf[ni*4+1]);
        }
        __syncthreads();

        if (C + 2 < TOTAL_CHUNKS) load_chunk(C + 2);

        if (c == 15) {
            float* eB = (float*)(smem + H1_EPI + EPI_B);
            float* eS = (float*)(smem + H1_EPI + EPI_S);
            int*   eI = (int*)(smem + H1_EPI + EPI_I);
            const int colBase = nt * BN + wn * 32 + tq * 2;
#pragma unroll
            for (int mi = 0; mi < 4; mi++) {
#pragma unroll
                for (int half = 0; half < 2; half++) {
                    const int row = wm * 64 + mi * 16 + half * 8 + t4;
                    float b = FLT_MAX, sv = FLT_MAX;
                    int   bi = 0x7FFFFFFF;
#pragma unroll
                    for (int ni = 0; ni < 4; ni++)
#pragma unroll
                        for (int cc = 0; cc < 2; cc++) {
                            const float v = acc[mi][ni][half * 2 + cc];
                            const int col = colBase + ni * 8 + cc;
                            if (v < b) { sv = b; b = v; bi = col; }
                            else       { sv = fminf(sv, v); }
                        }
#pragma unroll
                    for (int off = 1; off <= 2; off <<= 1) {
                        const float ob = __shfl_xor_sync(0xFFFFFFFFu, b, off);
                        const float os = __shfl_xor_sync(0xFFFFFFFFu, sv, off);
                        const int   oi = __shfl_xor_sync(0xFFFFFFFFu, bi, off);
                        if (ob < b || (ob == b && oi < bi)) { sv = fminf(b, os); b = ob; bi = oi; }
                        else                                { sv = fminf(sv, ob); }
                    }
                    if (tq == 0) { eB[row*4+wn] = b; eS[row*4+wn] = sv; eI[row*4+wn] = bi; }
                }
            }
            __syncthreads();
            if (tid < BM) {
#pragma unroll
                for (int w = 0; w < 4; w++) {
                    const float b = eB[tid*4+w], sv = eS[tid*4+w];
                    const int   bi = eI[tid*4+w];
                    if (b < rBest || (b == rBest && bi < rIdx)) {
                        rSec = fminf(rBest, sv); rBest = b; rIdx = bi;
                    } else {
                        rSec = fminf(rSec, fminf(b, sv));
                    }
                }
            }
            __syncthreads();
        }
    }

    if (tid < BM) {
        const int row = rowBase + tid;
        g_argmin[row] = rIdx;
        if (rSec - rBest < TAU1) {
            const int p = atomicAdd(&g_wl_count, 1);
            if (p < WL_CAP) g_wl[p] = row;
        }
    }
}

// ---------------------------------------------------------------------------
// Compact: build hi/lo bf16 split of flagged z rows; zero-pad to 128 multiple.
// ---------------------------------------------------------------------------
__global__ __launch_bounds__(128)
void vq_compact_kernel(const float* __restrict__ z) {
    const int cnt = min(g_wl_count, WL_CAP);
    const int nPad = (cnt + BM - 1) & ~(BM - 1);
    const int r = blockIdx.x;
    if (r >= nPad) return;
    const int tid = threadIdx.x;
    __nv_bfloat16* dh = g_rzh + (size_t)r * DIM;
    __nv_bfloat16* dl = g_rzl + (size_t)r * DIM;
    if (r < cnt) {
        const float* src = z + (size_t)g_wl[r] * DIM;
#pragma unroll
        for (int i = 0; i < DIM / 128; i++) {
            const float v = src[tid + i * 128];
            const __nv_bfloat16 h = __float2bfloat16(v);
            dh[tid + i * 128] = h;
            dl[tid + i * 128] = __float2bfloat16(v - __bfloat162float(h));
        }
    } else {
#pragma unroll
        for (int i = 0; i < DIM / 128; i++) {
            dh[tid + i * 128] = __float2bfloat16(0.0f);
            dl[tid + i * 128] = __float2bfloat16(0.0f);
        }
    }
}

// ---------------------------------------------------------------------------
// hmma2: 3-pass bf16 GEMM (ah*bh + al*bh + ah*bl) on compacted flagged rows.
// ---------------------------------------------------------------------------
__global__ __launch_bounds__(GEMM_THREADS)
void vq_hmma2_kernel() {
    const int cnt = min(g_wl_count, WL_CAP);
    const int rowBase = blockIdx.x * BM;
    if (rowBase >= cnt) return;

    extern __shared__ char smem[];
    const uint32_t sb = smem_to_u32(smem);
    const int tid  = threadIdx.x;
    const int wid  = tid >> 5;
    const int lane = tid & 31;
    const int wm   = wid >> 2;
    const int wn   = wid & 3;
    const int t4   = lane >> 2;
    const int tq   = lane & 3;

    auto load_chunk = [&](int C) {
        const int nt = C >> 4, c = C & 15, s = C & 1;
        const uint32_t stage = sb + s * H2_STAGE;
        const int koff = c * KC;
        const int ntBase = nt * BN;
#pragma unroll
        for (int i = 0; i < 4; i++) {
            const int sg = tid + i * 256;
            const int row = sg >> 3, sc = sg & 7;
            const uint32_t so = SWZ128(row * 128 + sc * 16);
            const size_t ga = (size_t)(rowBase + row) * DIM + koff + sc * 8;
            const size_t gb = (size_t)(ntBase + row) * DIM + koff + sc * 8;
            CP_ASYNC16(stage + H2_A_HI + so, g_rzh + ga);
            CP_ASYNC16(stage + H2_A_LO + so, g_rzl + ga);
            CP_ASYNC16(stage + H2_B_HI + so, g_cbh + gb);
            CP_ASYNC16(stage + H2_B_LO + so, g_cbl + gb);
        }
        CP_COMMIT();
    };

    float acc[4][4][4];
    float rBest = FLT_MAX, rSec = FLT_MAX;
    int   rIdx = 0x7FFFFFFF;

    const int am  = lane >> 3;
    const int ar  = lane & 7;
    const int aRow = ((am & 1) << 3) + ar;
    const int aColB = (am >> 1) << 4;
    const int bRow = ((am >> 1) << 3) + ar;
    const int bColB = (am & 1) << 4;

    load_chunk(0);
    load_chunk(1);

    for (int C = 0; C < TOTAL_CHUNKS; C++) {
        const int s = C & 1, nt = C >> 4, c = C & 15;
        if (C < TOTAL_CHUNKS - 1) { CP_WAIT1(); } else { CP_WAIT0(); }
        __syncthreads();

        if (c == 0) {
#pragma unroll
            for (int mi = 0; mi < 4; mi++)
#pragma unroll
                for (int ni = 0; ni < 4; ni++)
#pragma unroll
                    for (int r = 0; r < 4; r++) acc[mi][ni][r] = 0.0f;
        }

        const uint32_t stage = sb + s * H2_STAGE;
        const uint32_t aHi = stage + H2_A_HI, aLo = stage + H2_A_LO;
        const uint32_t bHi = stage + H2_B_HI, bLo = stage + H2_B_LO;

#pragma unroll
        for (int ks = 0; ks < 4; ks++) {
            const int kb = ks * 32;
            uint32_t ah[16], bh[16], xf[16];
#pragma unroll
            for (int mi = 0; mi < 4; mi++) {
                const int row = wm * 64 + mi * 16 + aRow;
                LDMATRIX_X4(ah[mi*4+0], ah[mi*4+1], ah[mi*4+2], ah[mi*4+3],
                            aHi + SWZ128(row * 128 + kb + aColB));
            }
#pragma unroll
            for (int np = 0; np < 2; np++) {
                const int nrow = wn * 32 + np * 16 + bRow;
                LDMATRIX_X4(bh[np*8+0], bh[np*8+1], bh[np*8+4], bh[np*8+5],
                            bHi + SWZ128(nrow * 128 + kb + bColB));
            }
#pragma unroll
            for (int mi = 0; mi < 4; mi++)
#pragma unroll
                for (int ni = 0; ni < 4; ni++)
                    MMA_BF16(acc[mi][ni][0], acc[mi][ni][1], acc[mi][ni][2], acc[mi][ni][3],
                             ah[mi*4+0], ah[mi*4+1], ah[mi*4+2], ah[mi*4+3],
                             bh[ni*4+0], bh[ni*4+1]);
#pragma unroll
            for (int mi = 0; mi < 4; mi++) {
                const int row = wm * 64 + mi * 16 + aRow;
                LDMATRIX_X4(xf[mi*4+0], xf[mi*4+1], xf[mi*4+2], xf[mi*4+3],
                            aLo + SWZ128(row * 128 + kb + aColB));
            }
#pragma unroll
            for (int mi = 0; mi < 4; mi++)
#pragma unroll
                for (int ni = 0; ni < 4; ni++)
                    MMA_BF16(acc[mi][ni][0], acc[mi][ni][1], acc[mi][ni][2], acc[mi][ni][3],
                             xf[mi*4+0], xf[mi*4+1], xf[mi*4+2], xf[mi*4+3],
                             bh[ni*4+0], bh[ni*4+1]);
#pragma unroll
            for (int np = 0; np < 2; np++) {
                const int nrow = wn * 32 + np * 16 + bRow;
                LDMATRIX_X4(xf[np*8+0], xf[np*8+1], xf[np*8+4], xf[np*8+5],
                            bLo + SWZ128(nrow * 128 + kb + bColB));
            }
#pragma unroll
            for (int mi = 0; mi < 4; mi++)
#pragma unroll
                for (int ni = 0; ni < 4; ni++)
                    MMA_BF16(acc[mi][ni][0], acc[mi][ni][1], acc[mi][ni][2], acc[mi][ni][3],
                             ah[mi*4+0], ah[mi*4+1], ah[mi*4+2], ah[mi*4+3],
                             xf[ni*4+0], xf[ni*4+1]);
        }
        __syncthreads();

        if (C + 2 < TOTAL_CHUNKS) load_chunk(C + 2);

        if (c == 15) {
            float* eB = (float*)(smem + H2_EPI + EPI_B);
            float* eS = (float*)(smem + H2_EPI + EPI_S);
            int*   eI = (int*)(smem + H2_EPI + EPI_I);
            const int colBase = nt * BN + wn * 32 + tq * 2;
#pragma unroll
            for (int mi = 0; mi < 4; mi++) {
#pragma unroll
                for (int half = 0; half < 2; half++) {
                    const int row = wm * 64 + mi * 16 + half * 8 + t4;
                    float b = FLT_MAX, sv = FLT_MAX;
                    int   bi = 0x7FFFFFFF;
#pragma unroll
                    for (int ni = 0; ni < 4; ni++)
#pragma unroll
                        for (int cc = 0; cc < 2; cc++) {
                            const float v = acc[mi][ni][half * 2 + cc];
                            const int col = colBase + ni * 8 + cc;
                            if (v < b) { sv = b; b = v; bi = col; }
                            else       { sv = fminf(sv, v); }
                        }
#pragma unroll
                    for (int off = 1; off <= 2; off <<= 1) {
                        const float ob = __shfl_xor_sync(0xFFFFFFFFu, b, off);
                        const float os = __shfl_xor_sync(0xFFFFFFFFu, sv, off);
                        const int   oi = __shfl_xor_sync(0xFFFFFFFFu, bi, off);
                        if (ob < b || (ob == b && oi < bi)) { sv = fminf(b, os); b = ob; bi = oi; }
                        else                                { sv = fminf(sv, ob); }
                    }
                    if (tq == 0) { eB[row*4+wn] = b; eS[row*4+wn] = sv; eI[row*4+wn] = bi; }
                }
            }
            __syncthreads();
            if (tid < BM) {
#pragma unroll
                for (int w = 0; w < 4; w++) {
                    const float b = eB[tid*4+w], sv = eS[tid*4+w];
                    const int   bi = eI[tid*4+w];
                    if (b < rBest || (b == rBest && bi < rIdx)) {
                        rSec = fminf(rBest, sv); rBest = b; rIdx = bi;
                    } else {
                        rSec = fminf(rSec, fminf(b, sv));
                    }
                }
            }
            __syncthreads();
        }
    }

    if (tid < BM && rowBase + tid < cnt) {
        const int grow = g_wl[rowBase + tid];
        g_argmin[grow] = rIdx;
        if (rSec - rBest < TAU2) {
            const int p = atomicAdd(&g_wl2_count, 1);
            if (p < WL2_CAP) g_wl2[p] = grow;
        }
    }
}

// ---------------------------------------------------------------------------
// refine2: exact pass on second-level worklist (fp32 rescore -> fp64 finish).
// ---------------------------------------------------------------------------
__global__ __launch_bounds__(256)
void vq_refine2_kernel(const float* __restrict__ A) {
    __shared__ float  zs[DIM];
    __shared__ float  dots[KCB];
    __shared__ float  red[256];
    __shared__ int    cands[MAX_CAND];
    __shared__ double cval[MAX_CAND];
    __shared__ int    ncand;

    const int tid  = threadIdx.x;
    const int lane = tid & 31;
    const int wrp  = tid >> 5;
    const int cnt  = min(g_wl2_count, WL2_CAP);

    for (int wi = blockIdx.x; wi < cnt; wi += gridDim.x) {
        const int row = g_wl2[wi];
#pragma unroll
        for (int i = 0; i < DIM / 256; i++)
            zs[tid + i * 256] = A[(size_t)row * DIM + tid + i * 256];
        if (tid == 0) ncand = 0;
        __syncthreads();

        const float4* z4 = (const float4*)zs;
        float localMin = FLT_MAX;
        for (int k = tid; k < KCB; k += 256) {
            const float4* c4 = (const float4*)(g_cbT + (size_t)k * DIM);
            float sacc = 0.0f;
#pragma unroll 8
            for (int d = 0; d < DIM / 4; d++) {
                const float4 cc = c4[d];
                const float4 zz = z4[d];
                sacc = fmaf(cc.x, zz.x, sacc);
                sacc = fmaf(cc.y, zz.y, sacc);
                sacc = fmaf(cc.z, zz.z, sacc);
                sacc = fmaf(cc.w, zz.w, sacc);
            }
            dots[k] = sacc;
            localMin = fminf(localMin, sacc);
        }
        red[tid] = localMin;
        __syncthreads();
        for (int off = 128; off > 0; off >>= 1) {
            if (tid < off) red[tid] = fminf(red[tid], red[tid + off]);
            __syncthreads();
        }
        const float bmin = red[0];

        for (int k = tid; k < KCB; k += 256) {
            if (dots[k] < bmin + TAU3) {
                const int p = atomicAdd(&ncand, 1);
                if (p < MAX_CAND) cands[p] = k;
            }
        }
        __syncthreads();
        const int nc = min(ncand, MAX_CAND);

        for (int ci = wrp; ci < nc; ci += 8) {
            const int k = cands[ci];
            const float* cbp = g_cbT + (size_t)k * DIM;
            double sd = 0.0;
            for (int d = lane; d < DIM; d += 32)
                sd += (double)cbp[d] * (double)zs[d];
#pragma unroll
            for (int off = 16; off > 0; off >>= 1)
                sd += __shfl_down_sync(0xFFFFFFFFu, sd, off);
            if (lane == 0) cval[ci] = sd;
        }
        __syncthreads();

        if (tid == 0) {
            double bv = cval[0];
            int    bi = cands[0];
            for (int c2 = 1; c2 < nc; c2++) {
                const double v = cval[c2];
                const int    x = cands[c2];
                if (v < bv || (v == bv && x < bi)) { bv = v; bi = x; }
            }
            g_argmin[row] = bi;
        }
        __syncthreads();
    }
}

// ---------------------------------------------------------------------------
// Gather: out[n][:] = g_cbT[argmin[n]][:]
// ---------------------------------------------------------------------------
__global__ void vq_gather_kernel(float* __restrict__ out) {
    const int n = blockIdx.x;
    const int idx = g_argmin[n];
    const float4* src = (const float4*)(g_cbT + (size_t)idx * DIM);
    float4* dst = (float4*)(out + (size_t)n * DIM);
    dst[threadIdx.x] = src[threadIdx.x];
}

// ---------------------------------------------------------------------------
extern "C" void kernel_launch(void* const* d_in, const int* in_sizes, int n_in,
                              void* d_out, int out_size) {
    const float* z  = (const float*)d_in[0];
    const float* cb = (const float*)d_in[1];
    float* out = (float*)d_out;

    cudaFuncSetAttribute(vq_hmma1_kernel, cudaFuncAttributeMaxDynamicSharedMemorySize, H1_SMEM);
    cudaFuncSetAttribute(vq_hmma2_kernel, cudaFuncAttributeMaxDynamicSharedMemorySize, H2_SMEM);

    dim3 tgrid(KCB / 32, DIM / 32);
    dim3 tblk(32, 8);
    vq_prep_cb<<<tgrid, tblk>>>(cb);
    vq_prep_z<<<8192, 256>>>(z);

    vq_hmma1_kernel<<<N_ROWS / BM, GEMM_THREADS, H1_SMEM>>>();

    vq_compact_kernel<<<WL_CAP, 128>>>(z);
    vq_hmma2_kernel<<<WL_CAP / BM, GEMM_THREADS, H2_SMEM>>>();

    vq_refine2_kernel<<<512, 256>>>(z);
    vq_gather_kernel<<<N_ROWS, 256>>>(out);
}

// round 10
// speedup vs baseline: 2.5163x; 1.1183x over previous
#include <cuda_runtime.h>
#include <cuda_bf16.h>
#include <cstdint>
#include <cfloat>

#define N_ROWS 65536
#define DIM    1024
#define KCB    8192

#define TAU1     0.28f     // 1-pass bf16 margin threshold (>=8 sigma)
#define TAU2     2.0e-3f   // 3-pass margin threshold
#define TAU3     2.0e-3f   // exact-refine candidate window
#define WL_CAP   16384
#define WL2_CAP  2048
#define MAX_CAND 64
#define NSPLIT   8         // hmma2 N-dimension split factor

#define BM 128
#define BN 128
#define KC 64
#define N_TILES (KCB / BN)                        // 64
#define TILES_PER_SPLIT (N_TILES / NSPLIT)        // 8
#define CHUNKS_PER_TILE (DIM / KC)                // 16
#define TOTAL_CHUNKS (N_TILES * CHUNKS_PER_TILE)  // 1024
#define SPLIT_CHUNKS (TILES_PER_SPLIT * CHUNKS_PER_TILE)  // 128
#define GEMM_THREADS 256

// ---- hmma1 SMEM layout (1-pass): stage = A(16K) + B(16K) ----
#define H1_STAGE   32768
#define H1_A       0
#define H1_B       16384
#define H1_EPI     (2 * H1_STAGE)
#define EPI_B      0
#define EPI_S      2048
#define EPI_I      4096
#define H1_SMEM    (H1_EPI + 6144)                // 71680

// ---- hmma2 SMEM layout (3-pass): stage = Ah+Al+Bh+Bl (64K) ----
#define H2_STAGE   65536
#define H2_A_HI    0
#define H2_A_LO    16384
#define H2_B_HI    32768
#define H2_B_LO    49152
#define H2_EPI     (2 * H2_STAGE)
#define H2_SMEM    (H2_EPI + 6144)                // 137216

// ---- scratch (__device__ globals; allocation-free rule) ----
__device__ __nv_bfloat16 g_zh[(size_t)N_ROWS * DIM];
__device__ __nv_bfloat16 g_cbh[(size_t)KCB * DIM];
__device__ __nv_bfloat16 g_cbl[(size_t)KCB * DIM];
__device__ float         g_cbT[(size_t)KCB * DIM];
__device__ __nv_bfloat16 g_rzh[(size_t)WL_CAP * DIM];
__device__ __nv_bfloat16 g_rzl[(size_t)WL_CAP * DIM];
__device__ int   g_argmin[N_ROWS];
__device__ int   g_wl[WL_CAP];
__device__ int   g_wl_count;
__device__ int   g_wl2[WL2_CAP];
__device__ int   g_wl2_count;
__device__ float g_pB[(size_t)WL_CAP * NSPLIT];   // hmma2 per-split best
__device__ float g_pS[(size_t)WL_CAP * NSPLIT];   // per-split second
__device__ int   g_pI[(size_t)WL_CAP * NSPLIT];   // per-split idx

// ============================ helpers ============================
__device__ __forceinline__ uint32_t smem_to_u32(const void* p) {
    uint32_t a;
    asm("{ .reg .u64 t; cvta.to.shared.u64 t, %1; cvt.u32.u64 %0, t; }" : "=r"(a) : "l"(p));
    return a;
}
#define SWZ128(o) ((o) ^ (((o) >> 3) & 0x70))

#define CP_ASYNC16(sm, g) \
    asm volatile("cp.async.cg.shared.global [%0], [%1], 16;" :: "r"(sm), "l"(g) : "memory")
#define CP_COMMIT()  asm volatile("cp.async.commit_group;" ::: "memory")
#define CP_WAIT1()   asm volatile("cp.async.wait_group 1;" ::: "memory")
#define CP_WAIT0()   asm volatile("cp.async.wait_group 0;" ::: "memory")

#define LDMATRIX_X4(r0, r1, r2, r3, a) \
    asm volatile("ldmatrix.sync.aligned.m8n8.x4.shared.b16 {%0,%1,%2,%3}, [%4];" \
                 : "=r"(r0), "=r"(r1), "=r"(r2), "=r"(r3) : "r"(a))

#define MMA_BF16(c0, c1, c2, c3, a0, a1, a2, a3, b0, b1) \
    asm volatile("mma.sync.aligned.m16n8k16.row.col.f32.bf16.bf16.f32 " \
                 "{%0,%1,%2,%3}, {%4,%5,%6,%7}, {%8,%9}, {%0,%1,%2,%3};" \
                 : "+f"(c0), "+f"(c1), "+f"(c2), "+f"(c3) \
                 : "r"(a0), "r"(a1), "r"(a2), "r"(a3), "r"(b0), "r"(b1))

// ---------------------------------------------------------------------------
// Prep 1: transpose codebook -> cbT fp32 + cbh/cbl bf16; reset worklists.
// ---------------------------------------------------------------------------
__global__ void vq_prep_cb(const float* __restrict__ cb) {
    if (blockIdx.x == 0 && blockIdx.y == 0 && threadIdx.x == 0 && threadIdx.y == 0) {
        g_wl_count = 0;
        g_wl2_count = 0;
    }
    __shared__ float tile[32][33];
    const int kBase = blockIdx.x * 32;
    const int dBase = blockIdx.y * 32;
    const int tx = threadIdx.x, ty = threadIdx.y;
#pragma unroll
    for (int i = 0; i < 4; i++)
        tile[ty + i * 8][tx] = cb[(size_t)(dBase + ty + i * 8) * KCB + (kBase + tx)];
    __syncthreads();
#pragma unroll
    for (int i = 0; i < 4; i++) {
        const float v = tile[tx][ty + i * 8];
        const size_t o = (size_t)(kBase + ty + i * 8) * DIM + (dBase + tx);
        g_cbT[o] = v;
        const __nv_bfloat16 h = __float2bfloat16(v);
        g_cbh[o] = h;
        g_cbl[o] = __float2bfloat16(v - __bfloat162float(h));
    }
}

// ---------------------------------------------------------------------------
// Prep 2: z -> bf16 (hi only).
// ---------------------------------------------------------------------------
__global__ void vq_prep_z(const float* __restrict__ z) {
    const size_t total4 = (size_t)N_ROWS * DIM / 4;
    const size_t stride = (size_t)gridDim.x * blockDim.x;
    const float4* z4 = (const float4*)z;
    __nv_bfloat162* h2 = (__nv_bfloat162*)g_zh;
    for (size_t t = (size_t)blockIdx.x * blockDim.x + threadIdx.x; t < total4; t += stride) {
        const float4 v = z4[t];
        h2[t * 2 + 0] = __nv_bfloat162(__float2bfloat16(v.x), __float2bfloat16(v.y));
        h2[t * 2 + 1] = __nv_bfloat162(__float2bfloat16(v.z), __float2bfloat16(v.w));
    }
}

// ---------------------------------------------------------------------------
// hmma1: single-pass bf16 GEMM + fused argmin with runner-up margin.
// ---------------------------------------------------------------------------
__global__ __launch_bounds__(GEMM_THREADS, 2)
void vq_hmma1_kernel() {
    extern __shared__ char smem[];
    const uint32_t sb = smem_to_u32(smem);
    const int tid  = threadIdx.x;
    const int wid  = tid >> 5;
    const int lane = tid & 31;
    const int wm   = wid >> 2;
    const int wn   = wid & 3;
    const int t4   = lane >> 2;
    const int tq   = lane & 3;
    const int rowBase = blockIdx.x * BM;

    auto load_chunk = [&](int C) {
        const int nt = C >> 4, c = C & 15, s = C & 1;
        const uint32_t stage = sb + s * H1_STAGE;
        const int koff = c * KC;
        const int ntBase = nt * BN;
#pragma unroll
        for (int i = 0; i < 4; i++) {
            const int sg = tid + i * 256;
            const int row = sg >> 3, sc = sg & 7;
            const uint32_t so = SWZ128(row * 128 + sc * 16);
            CP_ASYNC16(stage + H1_A + so, g_zh + (size_t)(rowBase + row) * DIM + koff + sc * 8);
            CP_ASYNC16(stage + H1_B + so, g_cbh + (size_t)(ntBase + row) * DIM + koff + sc * 8);
        }
        CP_COMMIT();
    };

    float acc[4][4][4];
    float rBest = FLT_MAX, rSec = FLT_MAX;
    int   rIdx = 0x7FFFFFFF;

    const int am  = lane >> 3;
    const int ar  = lane & 7;
    const int aRow = ((am & 1) << 3) + ar;
    const int aColB = (am >> 1) << 4;
    const int bRow = ((am >> 1) << 3) + ar;
    const int bColB = (am & 1) << 4;

    load_chunk(0);
    load_chunk(1);

    for (int C = 0; C < TOTAL_CHUNKS; C++) {
        const int s = C & 1, nt = C >> 4, c = C & 15;
        if (C < TOTAL_CHUNKS - 1) { CP_WAIT1(); } else { CP_WAIT0(); }
        __syncthreads();

        if (c == 0) {
#pragma unroll
            for (int mi = 0; mi < 4; mi++)
#pragma unroll
                for (int ni = 0; ni < 4; ni++)
#pragma unroll
                    for (int r = 0; r < 4; r++) acc[mi][ni][r] = 0.0f;
        }

        const uint32_t aB = sb + s * H1_STAGE + H1_A;
        const uint32_t bB = sb + s * H1_STAGE + H1_B;

#pragma unroll
        for (int ks = 0; ks < 4; ks++) {
            const int kb = ks * 32;
            uint32_t af[16], bf[16];
#pragma unroll
            for (int mi = 0; mi < 4; mi++) {
                const int row = wm * 64 + mi * 16 + aRow;
                LDMATRIX_X4(af[mi*4+0], af[mi*4+1], af[mi*4+2], af[mi*4+3],
                            aB + SWZ128(row * 128 + kb + aColB));
            }
#pragma unroll
            for (int np = 0; np < 2; np++) {
                const int nrow = wn * 32 + np * 16 + bRow;
                LDMATRIX_X4(bf[np*8+0], bf[np*8+1], bf[np*8+4], bf[np*8+5],
                            bB + SWZ128(nrow * 128 + kb + bColB));
            }
#pragma unroll
            for (int mi = 0; mi < 4; mi++)
#pragma unroll
                for (int ni = 0; ni < 4; ni++)
                    MMA_BF16(acc[mi][ni][0], acc[mi][ni][1], acc[mi][ni][2], acc[mi][ni][3],
                             af[mi*4+0], af[mi*4+1], af[mi*4+2], af[mi*4+3],
                             bf[ni*4+0], bf[ni*4+1]);
        }
        __syncthreads();

        if (C + 2 < TOTAL_CHUNKS) load_chunk(C + 2);

        if (c == 15) {
            float* eB = (float*)(smem + H1_EPI + EPI_B);
            float* eS = (float*)(smem + H1_EPI + EPI_S);
            int*   eI = (int*)(smem + H1_EPI + EPI_I);
            const int colBase = nt * BN + wn * 32 + tq * 2;
#pragma unroll
            for (int mi = 0; mi < 4; mi++) {
#pragma unroll
                for (int half = 0; half < 2; half++) {
                    const int row = wm * 64 + mi * 16 + half * 8 + t4;
                    float b = FLT_MAX, sv = FLT_MAX;
                    int   bi = 0x7FFFFFFF;
#pragma unroll
                    for (int ni = 0; ni < 4; ni++)
#pragma unroll
                        for (int cc = 0; cc < 2; cc++) {
                            const float v = acc[mi][ni][half * 2 + cc];
                            const int col = colBase + ni * 8 + cc;
                            if (v < b) { sv = b; b = v; bi = col; }
                            else       { sv = fminf(sv, v); }
                        }
#pragma unroll
                    for (int off = 1; off <= 2; off <<= 1) {
                        const float ob = __shfl_xor_sync(0xFFFFFFFFu, b, off);
                        const float os = __shfl_xor_sync(0xFFFFFFFFu, sv, off);
                        const int   oi = __shfl_xor_sync(0xFFFFFFFFu, bi, off);
                        if (ob < b || (ob == b && oi < bi)) { sv = fminf(b, os); b = ob; bi = oi; }
                        else                                { sv = fminf(sv, ob); }
                    }
                    if (tq == 0) { eB[row*4+wn] = b; eS[row*4+wn] = sv; eI[row*4+wn] = bi; }
                }
            }
            __syncthreads();
            if (tid < BM) {
#pragma unroll
                for (int w = 0; w < 4; w++) {
                    const float b = eB[tid*4+w], sv = eS[tid*4+w];
                    const int   bi = eI[tid*4+w];
                    if (b < rBest || (b == rBest && bi < rIdx)) {
                        rSec = fminf(rBest, sv); rBest = b; rIdx = bi;
                    } else {
                        rSec = fminf(rSec, fminf(b, sv));
                    }
                }
            }
            __syncthreads();
        }
    }

    if (tid < BM) {
        const int row = rowBase + tid;
        g_argmin[row] = rIdx;
        if (rSec - rBest < TAU1) {
            const int p = atomicAdd(&g_wl_count, 1);
            if (p < WL_CAP) g_wl[p] = row;
        }
    }
}

// ---------------------------------------------------------------------------
// Compact: build hi/lo bf16 split of flagged z rows; zero-pad to 128 multiple.
// ---------------------------------------------------------------------------
__global__ __launch_bounds__(128)
void vq_compact_kernel(const float* __restrict__ z) {
    const int cnt = min(g_wl_count, WL_CAP);
    const int nPad = (cnt + BM - 1) & ~(BM - 1);
    const int r = blockIdx.x;
    if (r >= nPad) return;
    const int tid = threadIdx.x;
    __nv_bfloat16* dh = g_rzh + (size_t)r * DIM;
    __nv_bfloat16* dl = g_rzl + (size_t)r * DIM;
    if (r < cnt) {
        const float* src = z + (size_t)g_wl[r] * DIM;
#pragma unroll
        for (int i = 0; i < DIM / 128; i++) {
            const float v = src[tid + i * 128];
            const __nv_bfloat16 h = __float2bfloat16(v);
            dh[tid + i * 128] = h;
            dl[tid + i * 128] = __float2bfloat16(v - __bfloat162float(h));
        }
    } else {
#pragma unroll
        for (int i = 0; i < DIM / 128; i++) {
            dh[tid + i * 128] = __float2bfloat16(0.0f);
            dl[tid + i * 128] = __float2bfloat16(0.0f);
        }
    }
}

// ---------------------------------------------------------------------------
// hmma2: 3-pass bf16 GEMM on compacted rows, N-SPLIT across blockIdx.y.
// Each CTA covers TILES_PER_SPLIT n-tiles; writes per-split partials.
// ---------------------------------------------------------------------------
__global__ __launch_bounds__(GEMM_THREADS)
void vq_hmma2_kernel() {
    const int cnt = min(g_wl_count, WL_CAP);
    const int rowBase = blockIdx.x * BM;
    if (rowBase >= cnt) return;
    const int split = blockIdx.y;
    const int ntBase0 = split * TILES_PER_SPLIT;

    extern __shared__ char smem[];
    const uint32_t sb = smem_to_u32(smem);
    const int tid  = threadIdx.x;
    const int wid  = tid >> 5;
    const int lane = tid & 31;
    const int wm   = wid >> 2;
    const int wn   = wid & 3;
    const int t4   = lane >> 2;
    const int tq   = lane & 3;

    auto load_chunk = [&](int C) {
        const int nt = ntBase0 + (C >> 4), c = C & 15, s = C & 1;
        const uint32_t stage = sb + s * H2_STAGE;
        const int koff = c * KC;
        const int ntBase = nt * BN;
#pragma unroll
        for (int i = 0; i < 4; i++) {
            const int sg = tid + i * 256;
            const int row = sg >> 3, sc = sg & 7;
            const uint32_t so = SWZ128(row * 128 + sc * 16);
            const size_t ga = (size_t)(rowBase + row) * DIM + koff + sc * 8;
            const size_t gb = (size_t)(ntBase + row) * DIM + koff + sc * 8;
            CP_ASYNC16(stage + H2_A_HI + so, g_rzh + ga);
            CP_ASYNC16(stage + H2_A_LO + so, g_rzl + ga);
            CP_ASYNC16(stage + H2_B_HI + so, g_cbh + gb);
            CP_ASYNC16(stage + H2_B_LO + so, g_cbl + gb);
        }
        CP_COMMIT();
    };

    float acc[4][4][4];
    float rBest = FLT_MAX, rSec = FLT_MAX;
    int   rIdx = 0x7FFFFFFF;

    const int am  = lane >> 3;
    const int ar  = lane & 7;
    const int aRow = ((am & 1) << 3) + ar;
    const int aColB = (am >> 1) << 4;
    const int bRow = ((am >> 1) << 3) + ar;
    const int bColB = (am & 1) << 4;

    load_chunk(0);
    load_chunk(1);

    for (int C = 0; C < SPLIT_CHUNKS; C++) {
        const int s = C & 1, ntl = C >> 4, c = C & 15;
        if (C < SPLIT_CHUNKS - 1) { CP_WAIT1(); } else { CP_WAIT0(); }
        __syncthreads();

        if (c == 0) {
#pragma unroll
            for (int mi = 0; mi < 4; mi++)
#pragma unroll
                for (int ni = 0; ni < 4; ni++)
#pragma unroll
                    for (int r = 0; r < 4; r++) acc[mi][ni][r] = 0.0f;
        }

        const uint32_t stage = sb + s * H2_STAGE;
        const uint32_t aHi = stage + H2_A_HI, aLo = stage + H2_A_LO;
        const uint32_t bHi = stage + H2_B_HI, bLo = stage + H2_B_LO;

#pragma unroll
        for (int ks = 0; ks < 4; ks++) {
            const int kb = ks * 32;
            uint32_t ah[16], bh[16], xf[16];
#pragma unroll
            for (int mi = 0; mi < 4; mi++) {
                const int row = wm * 64 + mi * 16 + aRow;
                LDMATRIX_X4(ah[mi*4+0], ah[mi*4+1], ah[mi*4+2], ah[mi*4+3],
                            aHi + SWZ128(row * 128 + kb + aColB));
            }
#pragma unroll
            for (int np = 0; np < 2; np++) {
                const int nrow = wn * 32 + np * 16 + bRow;
                LDMATRIX_X4(bh[np*8+0], bh[np*8+1], bh[np*8+4], bh[np*8+5],
                            bHi + SWZ128(nrow * 128 + kb + bColB));
            }
#pragma unroll
            for (int mi = 0; mi < 4; mi++)
#pragma unroll
                for (int ni = 0; ni < 4; ni++)
                    MMA_BF16(acc[mi][ni][0], acc[mi][ni][1], acc[mi][ni][2], acc[mi][ni][3],
                             ah[mi*4+0], ah[mi*4+1], ah[mi*4+2], ah[mi*4+3],
                             bh[ni*4+0], bh[ni*4+1]);
#pragma unroll
            for (int mi = 0; mi < 4; mi++) {
                const int row = wm * 64 + mi * 16 + aRow;
                LDMATRIX_X4(xf[mi*4+0], xf[mi*4+1], xf[mi*4+2], xf[mi*4+3],
                            aLo + SWZ128(row * 128 + kb + aColB));
            }
#pragma unroll
            for (int mi = 0; mi < 4; mi++)
#pragma unroll
                for (int ni = 0; ni < 4; ni++)
                    MMA_BF16(acc[mi][ni][0], acc[mi][ni][1], acc[mi][ni][2], acc[mi][ni][3],
                             xf[mi*4+0], xf[mi*4+1], xf[mi*4+2], xf[mi*4+3],
                             bh[ni*4+0], bh[ni*4+1]);
#pragma unroll
            for (int np = 0; np < 2; np++) {
                const int nrow = wn * 32 + np * 16 + bRow;
                LDMATRIX_X4(xf[np*8+0], xf[np*8+1], xf[np*8+4], xf[np*8+5],
                            bLo + SWZ128(nrow * 128 + kb + bColB));
            }
#pragma unroll
            for (int mi = 0; mi < 4; mi++)
#pragma unroll
                for (int ni = 0; ni < 4; ni++)
                    MMA_BF16(acc[mi][ni][0], acc[mi][ni][1], acc[mi][ni][2], acc[mi][ni][3],
                             ah[mi*4+0], ah[mi*4+1], ah[mi*4+2], ah[mi*4+3],
                             xf[ni*4+0], xf[ni*4+1]);
        }
        __syncthreads();

        if (C + 2 < SPLIT_CHUNKS) load_chunk(C + 2);

        if (c == 15) {
            float* eB = (float*)(smem + H2_EPI + EPI_B);
            float* eS = (float*)(smem + H2_EPI + EPI_S);
            int*   eI = (int*)(smem + H2_EPI + EPI_I);
            const int colBase = (ntBase0 + ntl) * BN + wn * 32 + tq * 2;
#pragma unroll
            for (int mi = 0; mi < 4; mi++) {
#pragma unroll
                for (int half = 0; half < 2; half++) {
                    const int row = wm * 64 + mi * 16 + half * 8 + t4;
                    float b = FLT_MAX, sv = FLT_MAX;
                    int   bi = 0x7FFFFFFF;
#pragma unroll
                    for (int ni = 0; ni < 4; ni++)
#pragma unroll
                        for (int cc = 0; cc < 2; cc++) {
                            const float v = acc[mi][ni][half * 2 + cc];
                            const int col = colBase + ni * 8 + cc;
                            if (v < b) { sv = b; b = v; bi = col; }
                            else       { sv = fminf(sv, v); }
                        }
#pragma unroll
                    for (int off = 1; off <= 2; off <<= 1) {
                        const float ob = __shfl_xor_sync(0xFFFFFFFFu, b, off);
                        const float os = __shfl_xor_sync(0xFFFFFFFFu, sv, off);
                        const int   oi = __shfl_xor_sync(0xFFFFFFFFu, bi, off);
                        if (ob < b || (ob == b && oi < bi)) { sv = fminf(b, os); b = ob; bi = oi; }
                        else                                { sv = fminf(sv, ob); }
                    }
                    if (tq == 0) { eB[row*4+wn] = b; eS[row*4+wn] = sv; eI[row*4+wn] = bi; }
                }
            }
            __syncthreads();
            if (tid < BM) {
#pragma unroll
                for (int w = 0; w < 4; w++) {
                    const float b = eB[tid*4+w], sv = eS[tid*4+w];
                    const int   bi = eI[tid*4+w];
                    if (b < rBest || (b == rBest && bi < rIdx)) {
                        rSec = fminf(rBest, sv); rBest = b; rIdx = bi;
                    } else {
                        rSec = fminf(rSec, fminf(b, sv));
                    }
                }
            }
            __syncthreads();
        }
    }

    if (tid < BM && rowBase + tid < cnt) {
        const size_t p = (size_t)(rowBase + tid) * NSPLIT + split;
        g_pB[p] = rBest;
        g_pS[p] = rSec;
        g_pI[p] = rIdx;
    }
}

// ---------------------------------------------------------------------------
// Combine: merge NSPLIT partials per flagged row -> argmin + wl2 flagging.
// ---------------------------------------------------------------------------
__global__ __launch_bounds__(256)
void vq_combine_kernel() {
    const int cnt = min(g_wl_count, WL_CAP);
    const int r = blockIdx.x * 256 + threadIdx.x;
    if (r >= cnt) return;

    float best = FLT_MAX, sec = FLT_MAX;
    int   bi = 0x7FFFFFFF;
#pragma unroll
    for (int sp = 0; sp < NSPLIT; sp++) {
        const size_t p = (size_t)r * NSPLIT + sp;
        const float b = g_pB[p];
        const float s = g_pS[p];
        const int   i = g_pI[p];
        if (b < best || (b == best && i < bi)) {
            sec = fminf(best, s);
            best = b; bi = i;
        } else {
            sec = fminf(sec, fminf(b, s));
        }
    }
    const int grow = g_wl[r];
    g_argmin[grow] = bi;
    if (sec - best < TAU2) {
        const int p = atomicAdd(&g_wl2_count, 1);
        if (p < WL2_CAP) g_wl2[p] = grow;
    }
}

// ---------------------------------------------------------------------------
// refine2: exact pass on second-level worklist (fp32 rescore -> fp64 finish).
// ---------------------------------------------------------------------------
__global__ __launch_bounds__(256)
void vq_refine2_kernel(const float* __restrict__ A) {
    __shared__ float  zs[DIM];
    __shared__ float  dots[KCB];
    __shared__ float  red[256];
    __shared__ int    cands[MAX_CAND];
    __shared__ double cval[MAX_CAND];
    __shared__ int    ncand;

    const int tid  = threadIdx.x;
    const int lane = tid & 31;
    const int wrp  = tid >> 5;
    const int cnt  = min(g_wl2_count, WL2_CAP);

    for (int wi = blockIdx.x; wi < cnt; wi += gridDim.x) {
        const int row = g_wl2[wi];
#pragma unroll
        for (int i = 0; i < DIM / 256; i++)
            zs[tid + i * 256] = A[(size_t)row * DIM + tid + i * 256];
        if (tid == 0) ncand = 0;
        __syncthreads();

        const float4* z4 = (const float4*)zs;
        float localMin = FLT_MAX;
        for (int k = tid; k < KCB; k += 256) {
            const float4* c4 = (const float4*)(g_cbT + (size_t)k * DIM);
            float sacc = 0.0f;
#pragma unroll 8
            for (int d = 0; d < DIM / 4; d++) {
                const float4 cc = c4[d];
                const float4 zz = z4[d];
                sacc = fmaf(cc.x, zz.x, sacc);
                sacc = fmaf(cc.y, zz.y, sacc);
                sacc = fmaf(cc.z, zz.z, sacc);
                sacc = fmaf(cc.w, zz.w, sacc);
            }
            dots[k] = sacc;
            localMin = fminf(localMin, sacc);
        }
        red[tid] = localMin;
        __syncthreads();
        for (int off = 128; off > 0; off >>= 1) {
            if (tid < off) red[tid] = fminf(red[tid], red[tid + off]);
            __syncthreads();
        }
        const float bmin = red[0];

        for (int k = tid; k < KCB; k += 256) {
            if (dots[k] < bmin + TAU3) {
                const int p = atomicAdd(&ncand, 1);
                if (p < MAX_CAND) cands[p] = k;
            }
        }
        __syncthreads();
        const int nc = min(ncand, MAX_CAND);

        for (int ci = wrp; ci < nc; ci += 8) {
            const int k = cands[ci];
            const float* cbp = g_cbT + (size_t)k * DIM;
            double sd = 0.0;
            for (int d = lane; d < DIM; d += 32)
                sd += (double)cbp[d] * (double)zs[d];
#pragma unroll
            for (int off = 16; off > 0; off >>= 1)
                sd += __shfl_down_sync(0xFFFFFFFFu, sd, off);
            if (lane == 0) cval[ci] = sd;
        }
        __syncthreads();

        if (tid == 0) {
            double bv = cval[0];
            int    bi = cands[0];
            for (int c2 = 1; c2 < nc; c2++) {
                const double v = cval[c2];
                const int    x = cands[c2];
                if (v < bv || (v == bv && x < bi)) { bv = v; bi = x; }
            }
            g_argmin[row] = bi;
        }
        __syncthreads();
    }
}

// ---------------------------------------------------------------------------
// Gather: out[n][:] = g_cbT[argmin[n]][:]
// ---------------------------------------------------------------------------
__global__ void vq_gather_kernel(float* __restrict__ out) {
    const int n = blockIdx.x;
    const int idx = g_argmin[n];
    const float4* src = (const float4*)(g_cbT + (size_t)idx * DIM);
    float4* dst = (float4*)(out + (size_t)n * DIM);
    dst[threadIdx.x] = src[threadIdx.x];
}

// ---------------------------------------------------------------------------
extern "C" void kernel_launch(void* const* d_in, const int* in_sizes, int n_in,
                              void* d_out, int out_size) {
    const float* z  = (const float*)d_in[0];
    const float* cb = (const float*)d_in[1];
    float* out = (float*)d_out;

    cudaFuncSetAttribute(vq_hmma1_kernel, cudaFuncAttributeMaxDynamicSharedMemorySize, H1_SMEM);
    cudaFuncSetAttribute(vq_hmma2_kernel, cudaFuncAttributeMaxDynamicSharedMemorySize, H2_SMEM);

    dim3 tgrid(KCB / 32, DIM / 32);
    dim3 tblk(32, 8);
    vq_prep_cb<<<tgrid, tblk>>>(cb);
    vq_prep_z<<<8192, 256>>>(z);

    vq_hmma1_kernel<<<N_ROWS / BM, GEMM_THREADS, H1_SMEM>>>();

    vq_compact_kernel<<<WL_CAP, 128>>>(z);

    dim3 h2grid(WL_CAP / BM, NSPLIT);
    vq_hmma2_kernel<<<h2grid, GEMM_THREADS, H2_SMEM>>>();
    vq_combine_kernel<<<WL_CAP / 256, 256>>>();

    vq_refine2_kernel<<<512, 256>>>(z);
    vq_gather_kernel<<<N_ROWS, 256>>>(out);
}